// round 2
// baseline (speedup 1.0000x reference)
#include <cuda_runtime.h>
#include <cuda_bf16.h>
#include <cooperative_groups.h>

namespace cg = cooperative_groups;

#define H_    4096
#define V_    32000
#define SEQ_  256
#define BATCH_ 64

// ---------------- device scratch (no cudaMalloc allowed) ----------------
__device__ float g_betaT[(size_t)V_ * H_];   // [v][h]  (500 MB)
__device__ float g_w1t[64 * 64 * 64];        // [blk][k][j]
__device__ float g_w0t[64 * 64 * 64];        // [blk][q][r]
__device__ float g_x[8 * 64 * 64 * 8];       // [cluster][i][k][b]   stage-1 input
__device__ float g_y[8 * 64 * 64 * 8];       // [cluster][j][i][b]   stage-2 input

// ---------------- beta transpose: betaT[v][h] = beta[h][v] ----------------
__global__ void k_tbeta(const float* __restrict__ beta) {
    __shared__ float tile[32][33];
    int v0 = blockIdx.x * 32;
    int h0 = blockIdx.y * 32;
    int tx = threadIdx.x, ty = threadIdx.y;   // block (32, 8)
#pragma unroll
    for (int r = 0; r < 32; r += 8)
        tile[ty + r][tx] = beta[(size_t)(h0 + ty + r) * V_ + (v0 + tx)];
    __syncthreads();
#pragma unroll
    for (int r = 0; r < 32; r += 8)
        g_betaT[(size_t)(v0 + ty + r) * H_ + (h0 + tx)] = tile[tx][ty + r];
}

// ---------------- weight transpose: wt[i][k][j] = w[i][j][k] ----------------
__global__ void k_tw(const float* __restrict__ w0, const float* __restrict__ w1) {
    int idx = blockIdx.x * 256 + threadIdx.x;   // i, j, k with k fastest
    int i = idx >> 12;
    int j = (idx >> 6) & 63;
    int k = idx & 63;
    int dst = (i * 64 + k) * 64 + j;
    g_w0t[dst] = w0[idx];
    g_w1t[dst] = w1[idx];
}

// ---------------- packed fp32x2 helpers ----------------
__device__ __forceinline__ unsigned long long pack2(float a, float b) {
    unsigned long long r;
    asm("mov.b64 %0, {%1, %2};" : "=l"(r) : "f"(a), "f"(b));
    return r;
}
__device__ __forceinline__ void unpack2(unsigned long long v, float& a, float& b) {
    asm("mov.b64 {%0, %1}, %2;" : "=f"(a), "=f"(b) : "l"(v));
}
__device__ __forceinline__ void ffma2(unsigned long long& acc,
                                      unsigned long long a, unsigned long long b) {
    asm("fma.rn.f32x2 %0, %1, %2, %0;" : "+l"(acc) : "l"(a), "l"(b));
}

// ---------------- one log-sum-exp block stage ----------------
// vle[hf][bb]: input for k = lane + 32*hf, batch-sub bb (log domain)
// wt_blk:  64x64 weights, [k][j] layout
// out_cluster: write y[j][bb] -> out_cluster[(j*64 + blk)*8 + bb]
__device__ __forceinline__ void monarch_stage(
    float (&vle)[2][8],
    const float* __restrict__ wt_blk,
    float* __restrict__ out_cluster,
    int blk, int lane, float (*esw)[8])
{
    // per-batch max over k (shfl butterfly; lane holds k=lane, lane+32)
    float m[8];
#pragma unroll
    for (int bb = 0; bb < 8; ++bb) {
        float mm = fmaxf(vle[0][bb], vle[1][bb]);
#pragma unroll
        for (int s = 16; s > 0; s >>= 1)
            mm = fmaxf(mm, __shfl_xor_sync(0xffffffffu, mm, s));
        m[bb] = mm;
    }

    // e = exp(v - m) -> smem (per-warp private tile)
#pragma unroll
    for (int hf = 0; hf < 2; ++hf) {
        int k = lane + 32 * hf;
        float4 e0, e1;
        e0.x = __expf(vle[hf][0] - m[0]);
        e0.y = __expf(vle[hf][1] - m[1]);
        e0.z = __expf(vle[hf][2] - m[2]);
        e0.w = __expf(vle[hf][3] - m[3]);
        e1.x = __expf(vle[hf][4] - m[4]);
        e1.y = __expf(vle[hf][5] - m[5]);
        e1.z = __expf(vle[hf][6] - m[6]);
        e1.w = __expf(vle[hf][7] - m[7]);
        *(float4*)&esw[k][0] = e0;
        *(float4*)&esw[k][4] = e1;
    }
    __syncwarp();

    // dot: lane computes outputs j = 2*lane, 2*lane+1 over 8 batch cols,
    // packed fp32x2 (4 b-pairs per j)
    unsigned long long acc[2][4];
#pragma unroll
    for (int jp = 0; jp < 2; ++jp)
#pragma unroll
        for (int bp = 0; bp < 4; ++bp) acc[jp][bp] = pack2(0.f, 0.f);

#pragma unroll 4
    for (int k = 0; k < 64; ++k) {
        float2 wv = *(const float2*)&wt_blk[k * 64 + 2 * lane];
        ulonglong2 ea = *(const ulonglong2*)&esw[k][0];   // e[b0..b3] packed
        ulonglong2 eb = *(const ulonglong2*)&esw[k][4];   // e[b4..b7] packed
        unsigned long long w0p = pack2(wv.x, wv.x);
        unsigned long long w1p = pack2(wv.y, wv.y);
        ffma2(acc[0][0], w0p, ea.x);
        ffma2(acc[0][1], w0p, ea.y);
        ffma2(acc[0][2], w0p, eb.x);
        ffma2(acc[0][3], w0p, eb.y);
        ffma2(acc[1][0], w1p, ea.x);
        ffma2(acc[1][1], w1p, ea.y);
        ffma2(acc[1][2], w1p, eb.x);
        ffma2(acc[1][3], w1p, eb.y);
    }

    // y = log(acc) + m ; scatter to permuted layout (L2 only, .cg)
#pragma unroll
    for (int jp = 0; jp < 2; ++jp) {
        int j = 2 * lane + jp;
        float y[8];
#pragma unroll
        for (int bp = 0; bp < 4; ++bp) {
            float lo, hi;
            unpack2(acc[jp][bp], lo, hi);
            y[2 * bp]     = __logf(lo) + m[2 * bp];
            y[2 * bp + 1] = __logf(hi) + m[2 * bp + 1];
        }
        float4* dst = (float4*)&out_cluster[((size_t)j * 64 + blk) * 8];
        __stcg(dst,     make_float4(y[0], y[1], y[2], y[3]));
        __stcg(dst + 1, make_float4(y[4], y[5], y[6], y[7]));
    }
}

// ---------------- main scan kernel: 8 clusters x 8 CTAs, 8 batch cols/cluster ----------------
__global__ __launch_bounds__(256, 1) __cluster_dims__(8, 1, 1)
void k_main(const int* __restrict__ ids) {
    __shared__ float es[8][64][8];     // per-warp exp tiles (16 KB)
    const int c    = blockIdx.x >> 3;  // cluster id
    const int r    = blockIdx.x & 7;   // rank in cluster
    const int w    = threadIdx.x >> 5;
    const int lane = threadIdx.x & 31;
    const int blk  = r * 8 + w;        // block owned in both stages
    cg::cluster_group cluster = cg::this_cluster();

    float* xc = &g_x[(size_t)c * 64 * 64 * 8];
    float* yc = &g_y[(size_t)c * 64 * 64 * 8];

    for (int t = SEQ_ - 1; t >= 1; --t) {
        // emission row pointers for this cluster's 8 batch columns
        int myid = 0;
        if (lane < 8) myid = ids[(c * 8 + lane) * SEQ_ + t];
        const float* bp[8];
#pragma unroll
        for (int bb = 0; bb < 8; ++bb)
            bp[bb] = g_betaT + (size_t)__shfl_sync(0xffffffffu, myid, bb) * H_;

        // ---------- stage 1 (w1): input x + emission ----------
        float vle[2][8];
#pragma unroll
        for (int hf = 0; hf < 2; ++hf) {
            int k = lane + 32 * hf;
            int h = blk * 64 + k;
            float xv[8];
            if (t == SEQ_ - 1) {
#pragma unroll
                for (int bb = 0; bb < 8; ++bb) xv[bb] = 0.f;
            } else {
                const float4* px = (const float4*)&xc[((size_t)blk * 64 + k) * 8];
                float4 a = __ldcg(px), b2 = __ldcg(px + 1);
                xv[0] = a.x;  xv[1] = a.y;  xv[2] = a.z;  xv[3] = a.w;
                xv[4] = b2.x; xv[5] = b2.y; xv[6] = b2.z; xv[7] = b2.w;
            }
#pragma unroll
            for (int bb = 0; bb < 8; ++bb)
                vle[hf][bb] = xv[bb] + __ldg(bp[bb] + h);
        }
        monarch_stage(vle, &g_w1t[blk * 4096], yc, blk, lane, es[w]);
        cluster.sync();

        // ---------- stage 2 (w0): input y (already permuted) ----------
#pragma unroll
        for (int hf = 0; hf < 2; ++hf) {
            int q = lane + 32 * hf;
            const float4* py = (const float4*)&yc[((size_t)blk * 64 + q) * 8];
            float4 a = __ldcg(py), b2 = __ldcg(py + 1);
            vle[hf][0] = a.x;  vle[hf][1] = a.y;  vle[hf][2] = a.z;  vle[hf][3] = a.w;
            vle[hf][4] = b2.x; vle[hf][5] = b2.y; vle[hf][6] = b2.z; vle[hf][7] = b2.w;
        }
        monarch_stage(vle, &g_w0t[blk * 4096], xc, blk, lane, es[w]);
        cluster.sync();
    }
}

// ---------------- final step: emission(t=0) + gamma contraction ----------------
__global__ void k_final(const int* __restrict__ ids,
                        const float* __restrict__ gexp,
                        float* __restrict__ out) {
    __shared__ float xs[H_];
    __shared__ float red[256];
    int b  = blockIdx.x;           // batch column
    int c  = b >> 3, bb = b & 7;
    int id0 = ids[b * SEQ_ + 0];
    const float* bp = g_betaT + (size_t)id0 * H_;
    const float* xc = &g_x[(size_t)c * 64 * 64 * 8];

    float mm = -3.4e38f;
    for (int h = threadIdx.x; h < H_; h += blockDim.x) {
        float xv = xc[((size_t)(h >> 6) * 64 + (h & 63)) * 8 + bb] + bp[h];
        xs[h] = xv;
        mm = fmaxf(mm, xv);
    }
    red[threadIdx.x] = mm;
    __syncthreads();
    for (int s = 128; s > 0; s >>= 1) {
        if (threadIdx.x < s)
            red[threadIdx.x] = fmaxf(red[threadIdx.x], red[threadIdx.x + s]);
        __syncthreads();
    }
    float M = red[0];
    __syncthreads();

    float ss = 0.f;
    for (int h = threadIdx.x; h < H_; h += blockDim.x)
        ss += gexp[h] * __expf(xs[h] - M);
    red[threadIdx.x] = ss;
    __syncthreads();
    for (int s = 128; s > 0; s >>= 1) {
        if (threadIdx.x < s)
            red[threadIdx.x] += red[threadIdx.x + s];
        __syncthreads();
    }
    if (threadIdx.x == 0) out[b] = __logf(red[0]) + M;
}

// ---------------- launch ----------------
extern "C" void kernel_launch(void* const* d_in, const int* in_sizes, int n_in,
                              void* d_out, int out_size) {
    const float* w0   = (const float*)d_in[0];
    const float* w1   = (const float*)d_in[1];
    const float* beta = (const float*)d_in[2];
    const float* gexp = (const float*)d_in[3];
    const int*   ids  = (const int*)d_in[4];
    float*       out  = (float*)d_out;

    k_tbeta<<<dim3(V_ / 32, H_ / 32), dim3(32, 8)>>>(beta);
    k_tw<<<(64 * 64 * 64) / 256, 256>>>(w0, w1);
    k_main<<<64, 256>>>(ids);
    k_final<<<64, 256>>>(ids, gexp, out);
}

// round 4
// speedup vs baseline: 1.0389x; 1.0389x over previous
#include <cuda_runtime.h>
#include <cooperative_groups.h>

namespace cg = cooperative_groups;

#define H_    4096
#define V_    32000
#define SEQ_  256
#define NC_   16     // clusters
#define CB_   4      // batch columns per cluster

typedef unsigned long long ull;

// ---------------- device scratch (no cudaMalloc allowed) ----------------
__device__ float    g_betaT[(size_t)V_ * H_];   // [v][h] raw beta, transposed
__device__ unsigned g_bmmbits[V_];              // keyed-bits running max over h
__device__ float    g_bmm[V_];                  // max_h beta[h][v]
__device__ float    g_w1t[64 * 64 * 64];        // [blk][k][j]
__device__ float    g_w0t[64 * 64 * 64];        // [blk][i][r]
__device__ float    g_x[NC_ * H_ * CB_];        // [c][h][b] linear state
__device__ float    g_y[NC_ * H_ * CB_];        // [c][h][b] stage exchange
__device__ unsigned g_redu[2][NC_ * CB_];       // double-buffered amax (float bits)
__device__ float    g_m[NC_ * CB_];             // per-batch accumulated log offset

// ---------------- helpers ----------------
__device__ __forceinline__ unsigned fkey(float f) {
    unsigned b = __float_as_uint(f);
    return (b & 0x80000000u) ? ~b : (b | 0x80000000u);
}
__device__ __forceinline__ ull pack2(float a, float b) {
    ull r;
    asm("mov.b64 %0, {%1, %2};" : "=l"(r) : "f"(a), "f"(b));
    return r;
}
__device__ __forceinline__ void unpack2(ull v, float& a, float& b) {
    asm("mov.b64 {%0, %1}, %2;" : "=f"(a), "=f"(b) : "l"(v));
}
__device__ __forceinline__ void ffma2(ull& acc, ull a, ull b) {
    asm("fma.rn.f32x2 %0, %1, %2, %0;" : "+l"(acc) : "l"(a), "l"(b));
}

// ---------------- beta transpose + per-token max (fused) ----------------
__global__ void k_tbeta(const float* __restrict__ beta) {
    __shared__ float tile[32][33];
    __shared__ float redm[8][32];
    int v0 = blockIdx.x * 32;
    int h0 = blockIdx.y * 32;
    int tx = threadIdx.x, ty = threadIdx.y;   // block (32, 8)
    float lm = -3.4e38f;
#pragma unroll
    for (int r = 0; r < 32; r += 8) {
        float v = beta[(size_t)(h0 + ty + r) * V_ + (v0 + tx)];
        tile[ty + r][tx] = v;
        lm = fmaxf(lm, v);
    }
    redm[ty][tx] = lm;
    __syncthreads();
#pragma unroll
    for (int r = 0; r < 32; r += 8)
        g_betaT[(size_t)(v0 + ty + r) * H_ + (h0 + tx)] = tile[tx][ty + r];
    if (ty == 0) {
        float m = redm[0][tx];
#pragma unroll
        for (int i = 1; i < 8; ++i) m = fmaxf(m, redm[i][tx]);
        atomicMax(&g_bmmbits[v0 + tx], fkey(m));
    }
}

// ---------------- convert keyed bits -> float bmm ----------------
__global__ void k_bmmfix() {
    int v = blockIdx.x * 256 + threadIdx.x;
    unsigned k = g_bmmbits[v];
    unsigned b = (k & 0x80000000u) ? (k ^ 0x80000000u) : ~k;
    g_bmm[v] = __uint_as_float(b);
}

// ---------------- weight transpose: wt[i][k][j] = w[i][j][k] ----------------
__global__ void k_tw(const float* __restrict__ w0, const float* __restrict__ w1) {
    int idx = blockIdx.x * 256 + threadIdx.x;
    int i = idx >> 12;
    int j = (idx >> 6) & 63;
    int k = idx & 63;
    int dst = (i * 64 + k) * 64 + j;
    g_w0t[dst] = w0[idx];
    g_w1t[dst] = w1[idx];
}

// ---------------- per-launch state init ----------------
__global__ void k_init() {
    int i = blockIdx.x * 256 + threadIdx.x;   // 65536 float4 = 262144 floats
    ((float4*)g_x)[i] = make_float4(1.f, 1.f, 1.f, 1.f);
    if (blockIdx.x == 0 && threadIdx.x < NC_ * CB_) {
        g_redu[0][threadIdx.x] = 0x3F800000u;   // 1.0f (first-step scale)
        g_redu[1][threadIdx.x] = 0u;            // zero (max identity)
    }
}

// ---------------- main scan: 16 clusters x 8 CTAs, 4 batch cols/cluster ----------------
struct SmemT {
    float w0[8][64][64];   // per-warp stage-2 weight tile (128 KB)
    ull   ue[8][64][6];    // per-warp dup-pair operand tile (pad 6 for banks)
};

__global__ __launch_bounds__(256, 1) __cluster_dims__(8, 1, 1)
void k_main(const int* __restrict__ ids) {
    extern __shared__ SmemT smem_[];
    SmemT* sm = smem_;
    const int c    = blockIdx.x >> 3;
    const int r    = blockIdx.x & 7;
    const int w    = threadIdx.x >> 5;
    const int lane = threadIdx.x & 31;
    const int blk  = r * 8 + w;
    cg::cluster_group cluster = cg::this_cluster();

    float* xc = &g_x[(size_t)c * H_ * CB_];
    float* yc = &g_y[(size_t)c * H_ * CB_];

    // ---- preload stage-1 weights into registers (packed j-pair) ----
    ull w1r[64];
#pragma unroll
    for (int k = 0; k < 64; ++k)
        w1r[k] = *(const ull*)&g_w1t[blk * 4096 + k * 64 + 2 * lane];

    // ---- stage-2 weights -> smem ----
    {
        const float4* src = (const float4*)&g_w0t[blk * 4096];
        float4* dst = (float4*)&sm->w0[w][0][0];
        for (int i = lane; i < 1024; i += 32) dst[i] = src[i];
    }
    __syncwarp();

    ull (*ue)[6]   = sm->ue[w];
    float (*sw0)[64] = sm->w0[w];

    // ---- first emission prefetch (t = SEQ-1) ----
    float em[2][4], bm[4];
    {
        int idv = 0;
        if (lane < 4) idv = __ldg(&ids[(c * 4 + lane) * SEQ_ + (SEQ_ - 1)]);
#pragma unroll
        for (int b = 0; b < 4; ++b) {
            int id = __shfl_sync(0xffffffffu, idv, b);
            const float* row = g_betaT + (size_t)id * H_ + blk * 64;
            em[0][b] = __ldg(row + lane);
            em[1][b] = __ldg(row + lane + 32);
            bm[b]    = __ldg(&g_bmm[id]);
        }
    }

    float macc = 0.f;
    const bool mthread = (r == 0 && w == 0 && lane < 4);

    for (int t = SEQ_ - 1; t >= 1; --t) {
        const int p1 = (t + 1) & 1;

        // exact scale of current X (written by previous step's stage-2)
        float4 scv = __ldcg((const float4*)&g_redu[p1][c * 4]);
        float rr0 = __fdividef(1.f, fmaxf(scv.x, 1e-35f));
        float rr1 = __fdividef(1.f, fmaxf(scv.y, 1e-35f));
        float rr2 = __fdividef(1.f, fmaxf(scv.z, 1e-35f));
        float rr3 = __fdividef(1.f, fmaxf(scv.w, 1e-35f));

        // ---- U = X * r * exp(beta - bmm)  -> dup-pair smem tile ----
        {
            float4 xa = __ldcg((const float4*)&xc[(blk * 64 + lane) * 4]);
            float4 xb = __ldcg((const float4*)&xc[(blk * 64 + lane + 32) * 4]);
            float u0 = xa.x * rr0 * __expf(em[0][0] - bm[0]);
            float u1 = xa.y * rr1 * __expf(em[0][1] - bm[1]);
            float u2 = xa.z * rr2 * __expf(em[0][2] - bm[2]);
            float u3 = xa.w * rr3 * __expf(em[0][3] - bm[3]);
            *(ulonglong2*)&ue[lane][0] = make_ulonglong2(pack2(u0, u0), pack2(u1, u1));
            *(ulonglong2*)&ue[lane][2] = make_ulonglong2(pack2(u2, u2), pack2(u3, u3));
            u0 = xb.x * rr0 * __expf(em[1][0] - bm[0]);
            u1 = xb.y * rr1 * __expf(em[1][1] - bm[1]);
            u2 = xb.z * rr2 * __expf(em[1][2] - bm[2]);
            u3 = xb.w * rr3 * __expf(em[1][3] - bm[3]);
            *(ulonglong2*)&ue[lane + 32][0] = make_ulonglong2(pack2(u0, u0), pack2(u1, u1));
            *(ulonglong2*)&ue[lane + 32][2] = make_ulonglong2(pack2(u2, u2), pack2(u3, u3));
        }
        __syncwarp();

        // ---- prefetch next step's emission while the dot runs ----
        {
            int tn = (t > 1) ? (t - 1) : 1;
            int idv = 0;
            if (lane < 4) idv = __ldg(&ids[(c * 4 + lane) * SEQ_ + tn]);
#pragma unroll
            for (int b = 0; b < 4; ++b) {
                int id = __shfl_sync(0xffffffffu, idv, b);
                const float* row = g_betaT + (size_t)id * H_ + blk * 64;
                em[0][b] = __ldg(row + lane);
                em[1][b] = __ldg(row + lane + 32);
                bm[b]    = __ldg(&g_bmm[id]);
            }
        }

        // ---- stage-1 dot: Y[j][b] = sum_k w1[j][k] * U[k][b] (w in regs) ----
        ull a0 = 0, a1 = 0, a2 = 0, a3 = 0;
#pragma unroll
        for (int k = 0; k < 64; ++k) {
            ulonglong2 e01 = *(const ulonglong2*)&ue[k][0];
            ulonglong2 e23 = *(const ulonglong2*)&ue[k][2];
            ffma2(a0, w1r[k], e01.x);
            ffma2(a1, w1r[k], e01.y);
            ffma2(a2, w1r[k], e23.x);
            ffma2(a3, w1r[k], e23.y);
        }
        {
            float y00, y01, y10, y11, y20, y21, y30, y31;
            unpack2(a0, y00, y01);
            unpack2(a1, y10, y11);
            unpack2(a2, y20, y21);
            unpack2(a3, y30, y31);
            __stcg((float4*)&yc[((2 * lane) * 64 + blk) * 4],
                   make_float4(y00, y10, y20, y30));
            __stcg((float4*)&yc[((2 * lane + 1) * 64 + blk) * 4],
                   make_float4(y01, y11, y21, y31));
        }
        cluster.sync();

        // reset the just-consumed scale buffer; accumulate log offset
        if (mthread) {
            __stcg(&g_redu[p1][c * 4 + lane], 0u);
            float sc = (lane == 0) ? scv.x : (lane == 1) ? scv.y
                     : (lane == 2) ? scv.z : scv.w;
            macc += __logf(fmaxf(sc, 1e-35f));
        }

        // ---- stage-2 operand tile from exchange buffer ----
        {
            float4 ya = __ldcg((const float4*)&yc[(blk * 64 + lane) * 4]);
            float4 yb = __ldcg((const float4*)&yc[(blk * 64 + lane + 32) * 4]);
            *(ulonglong2*)&ue[lane][0] = make_ulonglong2(pack2(ya.x, ya.x), pack2(ya.y, ya.y));
            *(ulonglong2*)&ue[lane][2] = make_ulonglong2(pack2(ya.z, ya.z), pack2(ya.w, ya.w));
            *(ulonglong2*)&ue[lane + 32][0] = make_ulonglong2(pack2(yb.x, yb.x), pack2(yb.y, yb.y));
            *(ulonglong2*)&ue[lane + 32][2] = make_ulonglong2(pack2(yb.z, yb.z), pack2(yb.w, yb.w));
        }
        __syncwarp();

        // ---- stage-2 dot: Z[rr][b] = sum_i w0[rr][i] * Y[i][b] (w in smem) ----
        ull b0 = 0, b1 = 0, b2 = 0, b3 = 0;
#pragma unroll
        for (int k = 0; k < 64; ++k) {
            ull wp = *(const ull*)&sw0[k][2 * lane];
            ulonglong2 e01 = *(const ulonglong2*)&ue[k][0];
            ulonglong2 e23 = *(const ulonglong2*)&ue[k][2];
            ffma2(b0, wp, e01.x);
            ffma2(b1, wp, e01.y);
            ffma2(b2, wp, e23.x);
            ffma2(b3, wp, e23.y);
        }
        {
            float z00, z01, z10, z11, z20, z21, z30, z31;
            unpack2(b0, z00, z01);
            unpack2(b1, z10, z11);
            unpack2(b2, z20, z21);
            unpack2(b3, z30, z31);
            __stcg((float4*)&xc[((2 * lane) * 64 + blk) * 4],
                   make_float4(z00, z10, z20, z30));
            __stcg((float4*)&xc[((2 * lane + 1) * 64 + blk) * 4],
                   make_float4(z01, z11, z21, z31));

            // per-batch max of this warp's outputs -> cluster amax slot
            float m0 = fmaxf(z00, z01);
            float m1 = fmaxf(z10, z11);
            float m2 = fmaxf(z20, z21);
            float m3 = fmaxf(z30, z31);
#pragma unroll
            for (int s = 16; s > 0; s >>= 1) {
                m0 = fmaxf(m0, __shfl_xor_sync(0xffffffffu, m0, s));
                m1 = fmaxf(m1, __shfl_xor_sync(0xffffffffu, m1, s));
                m2 = fmaxf(m2, __shfl_xor_sync(0xffffffffu, m2, s));
                m3 = fmaxf(m3, __shfl_xor_sync(0xffffffffu, m3, s));
            }
            if (lane == 0) {
                unsigned* slot = &g_redu[t & 1][c * 4];
                atomicMax(slot + 0, __float_as_uint(m0));
                atomicMax(slot + 1, __float_as_uint(m1));
                atomicMax(slot + 2, __float_as_uint(m2));
                atomicMax(slot + 3, __float_as_uint(m3));
            }
        }
        cluster.sync();
    }

    if (mthread) g_m[c * 4 + lane] = macc;
}

// ---------------- final: emission(t=0) + gamma contraction ----------------
__global__ void k_final(const int* __restrict__ ids,
                        const float* __restrict__ gexp,
                        float* __restrict__ out) {
    __shared__ float red[256];
    __shared__ float red2[256];
    int b = blockIdx.x, tid = threadIdx.x;
    int c = b >> 2, bb = b & 3;
    int id0 = __ldg(&ids[b * SEQ_]);
    float bmm0 = g_bmm[id0];
    const float* xc   = &g_x[(size_t)c * H_ * CB_];
    const float* brow = g_betaT + (size_t)id0 * H_;

    float s = 0.f;
    for (int h = tid; h < H_; h += 256)
        s += __ldg(&gexp[h]) * xc[h * 4 + bb] * __expf(brow[h] - bmm0);

    // per-token normalizers: thread tid handles timestep t = tid (0..255)
    float bs = g_bmm[__ldg(&ids[b * SEQ_ + tid])];

    red[tid] = s;
    red2[tid] = bs;
    __syncthreads();
    for (int st = 128; st > 0; st >>= 1) {
        if (tid < st) {
            red[tid]  += red[tid + st];
            red2[tid] += red2[tid + st];
        }
        __syncthreads();
    }
    if (tid == 0) out[b] = g_m[b] + red2[0] + logf(red[0]);
}

// ---------------- launch ----------------
extern "C" void kernel_launch(void* const* d_in, const int* in_sizes, int n_in,
                              void* d_out, int out_size) {
    const float* w0   = (const float*)d_in[0];
    const float* w1   = (const float*)d_in[1];
    const float* beta = (const float*)d_in[2];
    const float* gexp = (const float*)d_in[3];
    const int*   ids  = (const int*)d_in[4];
    float*       out  = (float*)d_out;

    cudaFuncSetAttribute(k_main, cudaFuncAttributeMaxDynamicSharedMemorySize,
                         (int)sizeof(SmemT));

    k_tbeta<<<dim3(V_ / 32, H_ / 32), dim3(32, 8)>>>(beta);
    k_bmmfix<<<V_ / 256, 256>>>();
    k_tw<<<(64 * 64 * 64) / 256, 256>>>(w0, w1);
    k_init<<<256, 256>>>();
    k_main<<<128, 256, sizeof(SmemT)>>>(ids);
    k_final<<<64, 256>>>(ids, gexp, out);
}